// round 15
// baseline (speedup 1.0000x reference)
#include <cuda_runtime.h>
#include <cuda_bf16.h>
#include <math.h>

#define NW 32
#define BB 64
#define TT 8192
#define KCH 8
#define CK (TT / KCH)     // 1024
#define KT 64             // fp32 per K-tile
#define NT (CK / KT)      // 16 tiles

typedef unsigned int u32;

__device__ float  g_pp[KCH * BB * NW * NW];    // per-chunk partials (2 MB)
__device__ float  g_pn[KCH * BB * NW * NW];
__device__ float  g_sum[KCH * 2 * BB * NW];
__device__ float  g_sq [KCH * 2 * BB * NW];
__device__ float  g_fpp[BB * NW * NW];         // per-b (1 - r) values
__device__ float  g_fpn[BB * NW * NW];
__device__ double g_tot[2];
__device__ int    g_ctr;
__device__ int    g_bctr[BB];                  // zero-init; self-cleaning

__device__ __forceinline__ void ldsm4(u32& r0, u32& r1, u32& r2, u32& r3, u32 a) {
    asm volatile("ldmatrix.sync.aligned.m8n8.x4.shared.b16 {%0,%1,%2,%3}, [%4];"
                 : "=r"(r0), "=r"(r1), "=r"(r2), "=r"(r3) : "r"(a));
}
__device__ __forceinline__ void ldsm2(u32& r0, u32& r1, u32 a) {
    asm volatile("ldmatrix.sync.aligned.m8n8.x2.shared.b16 {%0,%1}, [%2];"
                 : "=r"(r0), "=r"(r1) : "r"(a));
}
__device__ __forceinline__ void mma16816(float* c, u32 a0, u32 a1, u32 a2, u32 a3,
                                         u32 b0, u32 b1) {
    asm volatile("mma.sync.aligned.m16n8k16.row.col.f32.bf16.bf16.f32 "
                 "{%0,%1,%2,%3}, {%4,%5,%6,%7}, {%8,%9}, {%0,%1,%2,%3};"
                 : "+f"(c[0]), "+f"(c[1]), "+f"(c[2]), "+f"(c[3])
                 : "r"(a0), "r"(a1), "r"(a2), "r"(a3), "r"(b0), "r"(b1));
}
__device__ __forceinline__ u32 bpack(float lo, float hi) {
    __nv_bfloat162 t = __float22bfloat162_rn(make_float2(lo, hi));
    return *(u32*)&t;
}

// ============================================================================
// Kernel 1: bf16 mma.sync fused GEMM (PP + PN) + exact fp32 row stats.
// Last CTA per b folds the 8 chunk-partials AND computes (1 - r) directly
// (r is purely per-b), storing it to g_fpp/g_fpn.
// ============================================================================
__global__ void __launch_bounds__(128, 4)
k_gemm(const float* __restrict__ P, const float* __restrict__ Q) {
    __shared__ __align__(1024) char sm[2][64 * 128];   // 2 x 8 KB
    __shared__ float s_sx[2][NW], s_rv[2][NW];
    __shared__ int s_last;

    const int tid = threadIdx.x, lane = tid & 31, wid = tid >> 5;
    const int chunk = blockIdx.x, b = blockIdx.y;
    if (chunk == 0 && b == 0 && tid < 3) {
        if (tid < 2) g_tot[tid] = 0.0;
        else g_ctr = 0;
    }

    const int lrow = tid >> 4;
    const int li   = tid & 15;
    u32 goff[8], sdst[8];
    const u32 sbase = (u32)__cvta_generic_to_shared(sm);
#pragma unroll
    for (int u = 0; u < 8; u++) {
        int n = 8 * (u & 3) + lrow;
        goff[u] = (u32)((n * BB + b) * TT + chunk * CK + li * 4);
        int R = 8 * u + lrow;
        sdst[u] = sbase + (u32)(R * 128 + ((li * 8) ^ (lrow << 4)));
    }

    const int qd = lane >> 3, il = lane & 7;
    const u32 xm = (u32)(il << 4);
    u32 aB[2], bB[2];
#pragma unroll
    for (int mt = 0; mt < 2; mt++)
        aB[mt] = sbase + (u32)((16 * mt + (qd & 1) * 8 + il) * 128);
    const u32 c16A = (u32)((qd >> 1) * 16);
#pragma unroll
    for (int nt = 0; nt < 2; nt++)
        bB[nt] = sbase + (u32)((wid * 16 + nt * 8 + il) * 128);
    const u32 c16B = (u32)(((lane >> 3) & 1) * 16);

    float C[2][2][4];
#pragma unroll
    for (int i = 0; i < 2; i++)
#pragma unroll
        for (int j = 0; j < 2; j++)
#pragma unroll
            for (int k = 0; k < 4; k++) C[i][j][k] = 0.f;

    float acs[8], acq[8];
#pragma unroll
    for (int u = 0; u < 8; u++) { acs[u] = 0.f; acq[u] = 0.f; }

#define LDU(u, t) __ldg((const float4*)(((u) < 4 ? P : Q) + goff[u] + (t) * KT))
#define STU(u, boff) do {                                                     \
        float4 vv = v[u];                                                     \
        u32 w0 = bpack(vv.x, vv.y), w1 = bpack(vv.z, vv.w);                   \
        asm volatile("st.shared.v2.b32 [%0], {%1,%2};"                        \
                     :: "r"(sdst[u] + (boff)), "r"(w0), "r"(w1));             \
        acs[u] += (vv.x + vv.y) + (vv.z + vv.w);                              \
        acq[u] = fmaf(vv.x, vv.x, acq[u]); acq[u] = fmaf(vv.y, vv.y, acq[u]); \
        acq[u] = fmaf(vv.z, vv.z, acq[u]); acq[u] = fmaf(vv.w, vv.w, acq[u]); \
    } while (0)

    float4 v[8];
#pragma unroll
    for (int u = 0; u < 8; u++) v[u] = LDU(u, 0);
#pragma unroll
    for (int u = 0; u < 8; u++) { STU(u, 0); v[u] = LDU(u, 1); }
    __syncthreads();

    for (int t = 0; t < NT; t++) {
        const u32 boff = (u32)((t & 1) * 8192);
        if (t + 1 < NT) {
            const u32 woff = (u32)(((t + 1) & 1) * 8192);
#pragma unroll
            for (int u = 0; u < 8; u++) {
                STU(u, woff);
                if (t + 2 < NT) v[u] = LDU(u, t + 2);
            }
        }
#pragma unroll
        for (int j = 0; j < 4; j++) {
            u32 a[2][4], bq[2][2];
#pragma unroll
            for (int mt = 0; mt < 2; mt++)
                ldsm4(a[mt][0], a[mt][1], a[mt][2], a[mt][3],
                      aB[mt] + boff + (((u32)(j * 32) + c16A) ^ xm));
#pragma unroll
            for (int nt = 0; nt < 2; nt++)
                ldsm2(bq[nt][0], bq[nt][1],
                      bB[nt] + boff + (((u32)(j * 32) + c16B) ^ xm));
#pragma unroll
            for (int mt = 0; mt < 2; mt++)
#pragma unroll
                for (int nt = 0; nt < 2; nt++)
                    mma16816(C[mt][nt], a[mt][0], a[mt][1], a[mt][2], a[mt][3],
                             bq[nt][0], bq[nt][1]);
        }
        __syncthreads();
    }

    // ---- write C partials (warps 0-1: PP, 2-3: PN) ----
    {
        float* g0 = (wid < 2 ? g_pp : g_pn) + ((size_t)(chunk * BB + b)) * (NW * NW);
        const int g = lane >> 2, tq = lane & 3;
        const int wcol = (wid & 1) * 16;
#pragma unroll
        for (int mt = 0; mt < 2; mt++)
#pragma unroll
            for (int nt = 0; nt < 2; nt++) {
                int row0 = 16 * mt + g;
                int cc = wcol + nt * 8 + 2 * tq;
                *(float2*)(g0 + row0 * NW + cc) = make_float2(C[mt][nt][0], C[mt][nt][1]);
                *(float2*)(g0 + (row0 + 8) * NW + cc) = make_float2(C[mt][nt][2], C[mt][nt][3]);
            }
    }

    // ---- stats writeout ----
#pragma unroll
    for (int u = 0; u < 8; u++) {
#pragma unroll
        for (int off = 1; off < 16; off <<= 1) {
            acs[u] += __shfl_xor_sync(0xffffffffu, acs[u], off);
            acq[u] += __shfl_xor_sync(0xffffffffu, acq[u], off);
        }
        if (li == 0) {
            int set = u >> 2, n = 8 * (u & 3) + lrow;
            int idx = (chunk * 2 + set) * (BB * NW) + b * NW + n;
            g_sum[idx] = acs[u];  g_sq[idx] = acq[u];
        }
    }

    // ---- last CTA for this b: fold partials + stats, compute (1 - r) ----
    __threadfence();
    __syncthreads();
    if (tid == 0) s_last = (atomicAdd(&g_bctr[b], 1) == KCH - 1);
    __syncthreads();
    if (!s_last) return;
    __threadfence();                        // acquire other CTAs' partials

    if (tid < 2 * NW) {                     // fold stats for this b -> shared
        int set = tid >> 5, n = tid & 31;
        float ss = 0.f, s2 = 0.f;
#pragma unroll
        for (int c = 0; c < KCH; c++) {
            int a = (c * 2 + set) * (BB * NW) + b * NW + n;
            ss += g_sum[a]; s2 += g_sq[a];
        }
        s_sx[set][n] = ss;
        s_rv[set][n] = rsqrtf((float)TT * s2 - ss * ss);
    }
    __syncthreads();

    {
        const float4* spp = (const float4*)g_pp;
        const float4* spn = (const float4*)g_pn;
        float4* dpp = (float4*)g_fpp;
        float4* dpn = (float4*)g_fpn;
#pragma unroll
        for (int u = 0; u < 2; u++) {
            const int i4l = u * 128 + tid;          // 0..255 within b
            const int i4 = b * 256 + i4l;
            float4 s0 = make_float4(0.f, 0.f, 0.f, 0.f);
            float4 s1 = make_float4(0.f, 0.f, 0.f, 0.f);
#pragma unroll
            for (int c = 0; c < KCH; c++) {
                float4 x = spp[c * (BB * 256) + i4];
                s0.x += x.x; s0.y += x.y; s0.z += x.z; s0.w += x.w;
                float4 y = spn[c * (BB * 256) + i4];
                s1.x += y.x; s1.y += y.y; s1.z += y.z; s1.w += y.w;
            }
            const int f0 = i4l * 4;                 // flat nm index of .x
            const int n = f0 >> 5, m0 = f0 & 31;
            const float sxn = s_sx[0][n], rvn = s_rv[0][n];
            float4 o0, o1;
            {
                float sxy[4] = {s0.x, s0.y, s0.z, s0.w};
                float res[4];
#pragma unroll
                for (int j = 0; j < 4; j++)
                    res[j] = 1.f - ((float)TT * sxy[j] - sxn * s_sx[0][m0 + j])
                                   * rvn * s_rv[0][m0 + j];
                o0 = make_float4(res[0], res[1], res[2], res[3]);
            }
            {
                float sxy[4] = {s1.x, s1.y, s1.z, s1.w};
                float res[4];
#pragma unroll
                for (int j = 0; j < 4; j++)
                    res[j] = 1.f - ((float)TT * sxy[j] - sxn * s_sx[1][m0 + j])
                                   * rvn * s_rv[1][m0 + j];
                o1 = make_float4(res[0], res[1], res[2], res[3]);
            }
            dpp[i4] = o0;
            dpn[i4] = o1;
        }
        if (tid == 0) g_bctr[b] = 0;                // self-clean for replay
    }
}

// ============================================================================
// Kernel 2: pure reduction.  16 blocks x 128 threads; thread owns one (set,nm),
// sums (1-r) over b (coalesced, MLP=64), expf, block-reduce; last block
// writes the final scalar.
// ============================================================================
__global__ void __launch_bounds__(128) k_dmat(float* __restrict__ out) {
    const int tid = threadIdx.x;
    const int id = blockIdx.x * 128 + tid;          // 0..2047
    const int set = id >> 10, nm = id & 1023;
    const int n = nm >> 5, m = nm & 31;
    const float* src = set ? g_fpn : g_fpp;

    float acc = 0.f;
#pragma unroll
    for (int b = 0; b < BB; b++)
        acc += src[b * (NW * NW) + nm];
    float d = acc * (1.f / (float)BB);
    bool keep = set ? true : (m > n);
    double e = keep ? (double)expf(12.5f * d) : 0.0;  // 1/TAU = 12.5

#pragma unroll
    for (int off = 16; off > 0; off >>= 1)
        e += __shfl_xor_sync(0xffffffffu, e, off);

    __shared__ double s_w[4];
    const int w = tid >> 5, lane = tid & 31;
    if (lane == 0) s_w[w] = e;
    __syncthreads();

    if (tid == 0) {
        atomicAdd(&g_tot[set], s_w[0] + s_w[1] + s_w[2] + s_w[3]);
        __threadfence();
        int done = atomicAdd(&g_ctr, 1);
        if (done == 15) {
            double pos = atomicAdd(&g_tot[0], 0.0);
            double neg = atomicAdd(&g_tot[1], 0.0);
            out[0] = (float)log10(pos / neg + 1.0);
        }
    }
}

extern "C" void kernel_launch(void* const* d_in, const int* in_sizes, int n_in,
                              void* d_out, int out_size) {
    const float* P = (const float*)d_in[0];
    const float* Q = (const float*)d_in[1];
    k_gemm<<<dim3(KCH, BB), 128>>>(P, Q);
    k_dmat<<<16, 128>>>((float*)d_out);
}

// round 16
// speedup vs baseline: 1.0284x; 1.0284x over previous
#include <cuda_runtime.h>
#include <cuda_bf16.h>
#include <math.h>

#define NW 32
#define BB 64
#define TT 8192
#define KCH 8
#define CK (TT / KCH)     // 1024
#define KT 64             // fp32 per K-tile
#define NT (CK / KT)      // 16 tiles

typedef unsigned int u32;

__device__ float  g_pp[KCH * BB * NW * NW];    // per-chunk partials (2 MB)
__device__ float  g_pn[KCH * BB * NW * NW];
__device__ float  g_sum[KCH * 2 * BB * NW];
__device__ float  g_sq [KCH * 2 * BB * NW];
__device__ float  g_fpp[BB * NW * NW];         // per-b (1 - r) values
__device__ float  g_fpn[BB * NW * NW];
__device__ double g_tot[2];
__device__ int    g_ctr;
__device__ int    g_bctr[BB];                  // zero-init; self-cleaning

__device__ __forceinline__ void ldsm4(u32& r0, u32& r1, u32& r2, u32& r3, u32 a) {
    asm volatile("ldmatrix.sync.aligned.m8n8.x4.shared.b16 {%0,%1,%2,%3}, [%4];"
                 : "=r"(r0), "=r"(r1), "=r"(r2), "=r"(r3) : "r"(a));
}
__device__ __forceinline__ void ldsm2(u32& r0, u32& r1, u32 a) {
    asm volatile("ldmatrix.sync.aligned.m8n8.x2.shared.b16 {%0,%1}, [%2];"
                 : "=r"(r0), "=r"(r1) : "r"(a));
}
__device__ __forceinline__ void mma16816(float* c, u32 a0, u32 a1, u32 a2, u32 a3,
                                         u32 b0, u32 b1) {
    asm volatile("mma.sync.aligned.m16n8k16.row.col.f32.bf16.bf16.f32 "
                 "{%0,%1,%2,%3}, {%4,%5,%6,%7}, {%8,%9}, {%0,%1,%2,%3};"
                 : "+f"(c[0]), "+f"(c[1]), "+f"(c[2]), "+f"(c[3])
                 : "r"(a0), "r"(a1), "r"(a2), "r"(a3), "r"(b0), "r"(b1));
}
__device__ __forceinline__ u32 bpack(float lo, float hi) {
    __nv_bfloat162 t = __float22bfloat162_rn(make_float2(lo, hi));
    return *(u32*)&t;
}

// ============================================================================
// Kernel 1: bf16 mma.sync fused GEMM (PP + PN) + exact fp32 row stats.
// Last CTA per b folds the 8 chunk-partials AND computes (1 - r) directly
// (r is purely per-b), storing it to g_fpp/g_fpn.   (validated round 13/15)
// ============================================================================
__global__ void __launch_bounds__(128, 4)
k_gemm(const float* __restrict__ P, const float* __restrict__ Q) {
    __shared__ __align__(1024) char sm[2][64 * 128];   // 2 x 8 KB
    __shared__ float s_sx[2][NW], s_rv[2][NW];
    __shared__ int s_last;

    const int tid = threadIdx.x, lane = tid & 31, wid = tid >> 5;
    const int chunk = blockIdx.x, b = blockIdx.y;
    if (chunk == 0 && b == 0 && tid < 3) {
        if (tid < 2) g_tot[tid] = 0.0;
        else g_ctr = 0;
    }

    const int lrow = tid >> 4;
    const int li   = tid & 15;
    u32 goff[8], sdst[8];
    const u32 sbase = (u32)__cvta_generic_to_shared(sm);
#pragma unroll
    for (int u = 0; u < 8; u++) {
        int n = 8 * (u & 3) + lrow;
        goff[u] = (u32)((n * BB + b) * TT + chunk * CK + li * 4);
        int R = 8 * u + lrow;
        sdst[u] = sbase + (u32)(R * 128 + ((li * 8) ^ (lrow << 4)));
    }

    const int qd = lane >> 3, il = lane & 7;
    const u32 xm = (u32)(il << 4);
    u32 aB[2], bB[2];
#pragma unroll
    for (int mt = 0; mt < 2; mt++)
        aB[mt] = sbase + (u32)((16 * mt + (qd & 1) * 8 + il) * 128);
    const u32 c16A = (u32)((qd >> 1) * 16);
#pragma unroll
    for (int nt = 0; nt < 2; nt++)
        bB[nt] = sbase + (u32)((wid * 16 + nt * 8 + il) * 128);
    const u32 c16B = (u32)(((lane >> 3) & 1) * 16);

    float C[2][2][4];
#pragma unroll
    for (int i = 0; i < 2; i++)
#pragma unroll
        for (int j = 0; j < 2; j++)
#pragma unroll
            for (int k = 0; k < 4; k++) C[i][j][k] = 0.f;

    float acs[8], acq[8];
#pragma unroll
    for (int u = 0; u < 8; u++) { acs[u] = 0.f; acq[u] = 0.f; }

#define LDU(u, t) __ldg((const float4*)(((u) < 4 ? P : Q) + goff[u] + (t) * KT))
#define STU(u, boff) do {                                                     \
        float4 vv = v[u];                                                     \
        u32 w0 = bpack(vv.x, vv.y), w1 = bpack(vv.z, vv.w);                   \
        asm volatile("st.shared.v2.b32 [%0], {%1,%2};"                        \
                     :: "r"(sdst[u] + (boff)), "r"(w0), "r"(w1));             \
        acs[u] += (vv.x + vv.y) + (vv.z + vv.w);                              \
        acq[u] = fmaf(vv.x, vv.x, acq[u]); acq[u] = fmaf(vv.y, vv.y, acq[u]); \
        acq[u] = fmaf(vv.z, vv.z, acq[u]); acq[u] = fmaf(vv.w, vv.w, acq[u]); \
    } while (0)

    float4 v[8];
#pragma unroll
    for (int u = 0; u < 8; u++) v[u] = LDU(u, 0);
#pragma unroll
    for (int u = 0; u < 8; u++) { STU(u, 0); v[u] = LDU(u, 1); }
    __syncthreads();

    for (int t = 0; t < NT; t++) {
        const u32 boff = (u32)((t & 1) * 8192);
        if (t + 1 < NT) {
            const u32 woff = (u32)(((t + 1) & 1) * 8192);
#pragma unroll
            for (int u = 0; u < 8; u++) {
                STU(u, woff);
                if (t + 2 < NT) v[u] = LDU(u, t + 2);
            }
        }
#pragma unroll
        for (int j = 0; j < 4; j++) {
            u32 a[2][4], bq[2][2];
#pragma unroll
            for (int mt = 0; mt < 2; mt++)
                ldsm4(a[mt][0], a[mt][1], a[mt][2], a[mt][3],
                      aB[mt] + boff + (((u32)(j * 32) + c16A) ^ xm));
#pragma unroll
            for (int nt = 0; nt < 2; nt++)
                ldsm2(bq[nt][0], bq[nt][1],
                      bB[nt] + boff + (((u32)(j * 32) + c16B) ^ xm));
#pragma unroll
            for (int mt = 0; mt < 2; mt++)
#pragma unroll
                for (int nt = 0; nt < 2; nt++)
                    mma16816(C[mt][nt], a[mt][0], a[mt][1], a[mt][2], a[mt][3],
                             bq[nt][0], bq[nt][1]);
        }
        __syncthreads();
    }

    // ---- write C partials (warps 0-1: PP, 2-3: PN) ----
    {
        float* g0 = (wid < 2 ? g_pp : g_pn) + ((size_t)(chunk * BB + b)) * (NW * NW);
        const int g = lane >> 2, tq = lane & 3;
        const int wcol = (wid & 1) * 16;
#pragma unroll
        for (int mt = 0; mt < 2; mt++)
#pragma unroll
            for (int nt = 0; nt < 2; nt++) {
                int row0 = 16 * mt + g;
                int cc = wcol + nt * 8 + 2 * tq;
                *(float2*)(g0 + row0 * NW + cc) = make_float2(C[mt][nt][0], C[mt][nt][1]);
                *(float2*)(g0 + (row0 + 8) * NW + cc) = make_float2(C[mt][nt][2], C[mt][nt][3]);
            }
    }

    // ---- stats writeout ----
#pragma unroll
    for (int u = 0; u < 8; u++) {
#pragma unroll
        for (int off = 1; off < 16; off <<= 1) {
            acs[u] += __shfl_xor_sync(0xffffffffu, acs[u], off);
            acq[u] += __shfl_xor_sync(0xffffffffu, acq[u], off);
        }
        if (li == 0) {
            int set = u >> 2, n = 8 * (u & 3) + lrow;
            int idx = (chunk * 2 + set) * (BB * NW) + b * NW + n;
            g_sum[idx] = acs[u];  g_sq[idx] = acq[u];
        }
    }

    // ---- last CTA for this b: fold partials + stats, compute (1 - r) ----
    __threadfence();
    __syncthreads();
    if (tid == 0) s_last = (atomicAdd(&g_bctr[b], 1) == KCH - 1);
    __syncthreads();
    if (!s_last) return;
    __threadfence();                        // acquire other CTAs' partials

    if (tid < 2 * NW) {                     // fold stats for this b -> shared
        int set = tid >> 5, n = tid & 31;
        float ss = 0.f, s2 = 0.f;
#pragma unroll
        for (int c = 0; c < KCH; c++) {
            int a = (c * 2 + set) * (BB * NW) + b * NW + n;
            ss += g_sum[a]; s2 += g_sq[a];
        }
        s_sx[set][n] = ss;
        s_rv[set][n] = rsqrtf((float)TT * s2 - ss * ss);
    }
    __syncthreads();

    {
        const float4* spp = (const float4*)g_pp;
        const float4* spn = (const float4*)g_pn;
        float4* dpp = (float4*)g_fpp;
        float4* dpn = (float4*)g_fpn;
#pragma unroll
        for (int u = 0; u < 2; u++) {
            const int i4l = u * 128 + tid;          // 0..255 within b
            const int i4 = b * 256 + i4l;
            float4 s0 = make_float4(0.f, 0.f, 0.f, 0.f);
            float4 s1 = make_float4(0.f, 0.f, 0.f, 0.f);
#pragma unroll
            for (int c = 0; c < KCH; c++) {
                float4 x = spp[c * (BB * 256) + i4];
                s0.x += x.x; s0.y += x.y; s0.z += x.z; s0.w += x.w;
                float4 y = spn[c * (BB * 256) + i4];
                s1.x += y.x; s1.y += y.y; s1.z += y.z; s1.w += y.w;
            }
            const int f0 = i4l * 4;                 // flat nm index of .x
            const int n = f0 >> 5, m0 = f0 & 31;
            const float sxn = s_sx[0][n], rvn = s_rv[0][n];
            float4 o0, o1;
            {
                float sxy[4] = {s0.x, s0.y, s0.z, s0.w};
                float res[4];
#pragma unroll
                for (int j = 0; j < 4; j++)
                    res[j] = 1.f - ((float)TT * sxy[j] - sxn * s_sx[0][m0 + j])
                                   * rvn * s_rv[0][m0 + j];
                o0 = make_float4(res[0], res[1], res[2], res[3]);
            }
            {
                float sxy[4] = {s1.x, s1.y, s1.z, s1.w};
                float res[4];
#pragma unroll
                for (int j = 0; j < 4; j++)
                    res[j] = 1.f - ((float)TT * sxy[j] - sxn * s_sx[1][m0 + j])
                                   * rvn * s_rv[1][m0 + j];
                o1 = make_float4(res[0], res[1], res[2], res[3]);
            }
            dpp[i4] = o0;
            dpn[i4] = o1;
        }
        if (tid == 0) g_bctr[b] = 0;                // self-clean for replay
    }
}

// ============================================================================
// Kernel 2: parallel reduction over b.  128 blocks x 256 threads.
// Block owns 16 (set,nm) values: set = bid>>6, nm0 = (bid&63)*16.
// Thread (bg = tid>>4, nm_l = tid&15) sums 4 b-values (4 independent loads —
// latency covered at 30 regs).  16x16 shared fold, expf in warp 0, shfl
// reduce, double atomicAdd; 128-block counter finisher.
// ============================================================================
__global__ void __launch_bounds__(256) k_dmat(float* __restrict__ out) {
    const int bid = blockIdx.x, tid = threadIdx.x;
    const int set = bid >> 6;
    const int nm0 = (bid & 63) * 16;
    const int nm_l = tid & 15;
    const int bg   = tid >> 4;                  // 0..15
    const float* src = (set ? g_fpn : g_fpp) + nm0 + nm_l;

    float acc = 0.f;
#pragma unroll
    for (int j = 0; j < 4; j++)
        acc += src[(size_t)(bg * 4 + j) * (NW * NW)];

    __shared__ float s_p[16][17];
    s_p[bg][nm_l] = acc;
    __syncthreads();

    double e = 0.0;
    if (tid < 16) {
        float d = 0.f;
#pragma unroll
        for (int k = 0; k < 16; k++) d += s_p[k][tid];
        d *= (1.f / (float)BB);
        int nmf = nm0 + tid, n = nmf >> 5, m = nmf & 31;
        bool keep = set ? true : (m > n);
        if (keep) e = (double)expf(12.5f * d);  // 1/TAU = 12.5
    }
    if (tid < 32) {
#pragma unroll
        for (int off = 8; off > 0; off >>= 1)
            e += __shfl_xor_sync(0xffffffffu, e, off);
        if (tid == 0) {
            atomicAdd(&g_tot[set], e);
            __threadfence();
            int done = atomicAdd(&g_ctr, 1);
            if (done == 127) {
                double pos = atomicAdd(&g_tot[0], 0.0);
                double neg = atomicAdd(&g_tot[1], 0.0);
                out[0] = (float)log10(pos / neg + 1.0);
            }
        }
    }
}

extern "C" void kernel_launch(void* const* d_in, const int* in_sizes, int n_in,
                              void* d_out, int out_size) {
    const float* P = (const float*)d_in[0];
    const float* Q = (const float*)d_in[1];
    k_gemm<<<dim3(KCH, BB), 128>>>(P, Q);
    k_dmat<<<128, 256>>>((float*)d_out);
}